// round 13
// baseline (speedup 1.0000x reference)
#include <cuda_runtime.h>
#include <cuda_bf16.h>

#define DI __device__ __forceinline__

constexpr int Bn = 2, Sn = 2048, Dn = 1024, Hn = 16, DEPn = 64, BHn = 32, Mn = 4096;
constexpr long long OUT_ELEMS = (long long)Mn * Dn;
constexpr size_t AW = (size_t)Mn * 512;   // activation words per half-matrix
constexpr size_t WW = (size_t)Dn * 512;   // weight words per half-matrix

// scratch (__device__ globals: allocation-free rule)
__device__ unsigned g_Aph[3 * AW], g_Apl[3 * AW];   // split q,k,v
__device__ unsigned g_Wth[4 * WW], g_Wtl[4 * WW];   // transposed+split Wq,Wk,Wv,Wo
__device__ unsigned g_Qph[AW], g_Qpl[AW];           // head-split packed Q (pre-scaled)
__device__ unsigned g_Kph[AW], g_Kpl[AW];           // head-split packed K
__device__ float    g_Vt[(size_t)BHn * DEPn * Sn];  // V TRANSPOSED (bh, d, s) fp32
__device__ unsigned g_Oph[AW], g_Opl[AW];           // attention output, packed

DI void split2(float x, float y, unsigned& h, unsigned& l) {
    __nv_bfloat16 hx = __float2bfloat16(x), hy = __float2bfloat16(y);
    __nv_bfloat162 hp; hp.x = hx; hp.y = hy;
    h = *reinterpret_cast<unsigned*>(&hp);
    __nv_bfloat162 lp;
    lp.x = __float2bfloat16(x - __bfloat162float(hx));
    lp.y = __float2bfloat16(y - __bfloat162float(hy));
    l = *reinterpret_cast<unsigned*>(&lp);
}
DI void mma16(float* c, unsigned a0, unsigned a1, unsigned a2, unsigned a3,
              unsigned b0, unsigned b1) {
    asm volatile(
        "mma.sync.aligned.m16n8k16.row.col.f32.bf16.bf16.f32 "
        "{%0,%1,%2,%3}, {%4,%5,%6,%7}, {%8,%9}, {%0,%1,%2,%3};\n"
        : "+f"(c[0]), "+f"(c[1]), "+f"(c[2]), "+f"(c[3])
        : "r"(a0), "r"(a1), "r"(a2), "r"(a3), "r"(b0), "r"(b1));
}
DI void ldsm4(unsigned* r, unsigned addr) {
    asm volatile(
        "ldmatrix.sync.aligned.m8n8.x4.shared.b16 {%0,%1,%2,%3}, [%4];"
        : "=r"(r[0]), "=r"(r[1]), "=r"(r[2]), "=r"(r[3]) : "r"(addr));
}

// ---------------------------------------------------------------------------
// Prep: split activations q,k,v into packed bf16x2 hi/lo (no transpose).
// ---------------------------------------------------------------------------
__global__ __launch_bounds__(256) void split_act(const float* __restrict__ q,
                                                 const float* __restrict__ k,
                                                 const float* __restrict__ v) {
    const int z = blockIdx.y;
    const float* src = (z == 0) ? q : (z == 1) ? k : v;
    const size_t i = (size_t)blockIdx.x * 256 + threadIdx.x;
    const size_t base = z * AW + i * 4;
    float4 a = reinterpret_cast<const float4*>(src)[i * 2];
    float4 b = reinterpret_cast<const float4*>(src)[i * 2 + 1];
    split2(a.x, a.y, g_Aph[base + 0], g_Apl[base + 0]);
    split2(a.z, a.w, g_Aph[base + 1], g_Apl[base + 1]);
    split2(b.x, b.y, g_Aph[base + 2], g_Apl[base + 2]);
    split2(b.z, b.w, g_Aph[base + 3], g_Apl[base + 3]);
}

// ---------------------------------------------------------------------------
// Prep: transpose W (K x N) -> Wt[n][kpair], packed bf16x2 hi/lo.
// ---------------------------------------------------------------------------
struct W4 { const float* w[4]; };

__global__ __launch_bounds__(256) void transpose_split(W4 ws) {
    __shared__ float t[32][33];
    const int mat = blockIdx.z, kt = blockIdx.y, nt = blockIdx.x;
    const float* W = ws.w[mat];
    const int tid = threadIdx.x;
    const int rr = tid >> 5, cc = tid & 31;
#pragma unroll
    for (int p = 0; p < 4; ++p)
        t[rr + p * 8][cc] = W[(size_t)(kt * 32 + rr + p * 8) * Dn + nt * 32 + cc];
    __syncthreads();
#pragma unroll
    for (int p = 0; p < 2; ++p) {
        const int idx = tid + p * 256;
        const int n = idx >> 4, kp = idx & 15;
        unsigned h, l;
        split2(t[2 * kp][n], t[2 * kp + 1][n], h, l);
        const size_t o = (size_t)mat * WW + (size_t)(nt * 32 + n) * 512 + kt * 16 + kp;
        g_Wth[o] = h;
        g_Wtl[o] = l;
    }
}

// ---------------------------------------------------------------------------
// Projection GEMM: 128x128x64 tiles, split-bf16 3x, ldmatrix fragment loads.
// mode 0: fp32 flat. mode 1: packed head-split (scaled). mode 2: fp32 V^T.
// ---------------------------------------------------------------------------
struct PP3 {
    const unsigned *Ah[3], *Al[3], *Bh[3], *Bl[3];
    const float* bias[3];
    float scale[3];
    int mode[3];
    float* outF[3];
    unsigned *oPh[3], *oPl[3];
};

constexpr int TS = 36;
constexpr int PSMB = 4 * 128 * TS * 4;   // 73,728 B

__global__ __launch_bounds__(256, 2) void proj_gemm(PP3 pp) {
    extern __shared__ unsigned sm[];
    unsigned* Ah = sm;
    unsigned* Al = Ah + 128 * TS;
    unsigned* Bh = Al + 128 * TS;
    unsigned* Bl = Bh + 128 * TS;

    const int z = blockIdx.z;
    const unsigned* gAh = pp.Ah[z];
    const unsigned* gAl = pp.Al[z];
    const unsigned* gBh = pp.Bh[z];
    const unsigned* gBl = pp.Bl[z];
    const float* bias = pp.bias[z];
    const float scale = pp.scale[z];
    const int mode = pp.mode[z];

    const int tid = threadIdx.x, warp = tid >> 5, lane = tid & 31;
    const int gid = lane >> 2, tig = lane & 3;
    const int wm = (warp >> 2) * 64, wn = (warp & 3) * 32;
    const int bm0 = blockIdx.y * 128, bn0 = blockIdx.x * 128;
    const int row = tid >> 1, wq = (tid & 1) * 16;

    const unsigned sAh = (unsigned)__cvta_generic_to_shared(Ah);
    const unsigned sAl = (unsigned)__cvta_generic_to_shared(Al);
    const unsigned sBh = (unsigned)__cvta_generic_to_shared(Bh);
    const unsigned sBl = (unsigned)__cvta_generic_to_shared(Bl);
    // ldmatrix per-lane base offsets (bytes)
    const unsigned aoff = ((wm + (lane & 15)) * TS + ((lane >> 4) << 2)) * 4;
    const unsigned boff =
        ((wn + (lane & 7) + ((lane & 16) ? 8 : 0)) * TS + (((lane >> 3) & 1) << 2)) * 4;

    float c[4][4][4];
#pragma unroll
    for (int mi = 0; mi < 4; ++mi)
#pragma unroll
        for (int ni = 0; ni < 4; ++ni)
#pragma unroll
            for (int e = 0; e < 4; ++e) c[mi][ni][e] = 0.f;

    for (int kt = 0; kt < 16; ++kt) {
        const uint4* a_h = reinterpret_cast<const uint4*>(gAh + (size_t)(bm0 + row) * 512 + kt * 32 + wq);
        const uint4* a_l = reinterpret_cast<const uint4*>(gAl + (size_t)(bm0 + row) * 512 + kt * 32 + wq);
        const uint4* b_h = reinterpret_cast<const uint4*>(gBh + (size_t)(bn0 + row) * 512 + kt * 32 + wq);
        const uint4* b_l = reinterpret_cast<const uint4*>(gBl + (size_t)(bn0 + row) * 512 + kt * 32 + wq);
#pragma unroll
        for (int u = 0; u < 4; ++u) {
            *reinterpret_cast<uint4*>(&Ah[row * TS + wq + u * 4]) = a_h[u];
            *reinterpret_cast<uint4*>(&Al[row * TS + wq + u * 4]) = a_l[u];
            *reinterpret_cast<uint4*>(&Bh[row * TS + wq + u * 4]) = b_h[u];
            *reinterpret_cast<uint4*>(&Bl[row * TS + wq + u * 4]) = b_l[u];
        }
        __syncthreads();
#pragma unroll
        for (int ks = 0; ks < 4; ++ks) {
            unsigned ah[4][4], al[4][4], bh2[2][4], bl2[2][4];
#pragma unroll
            for (int mi = 0; mi < 4; ++mi) {
                ldsm4(ah[mi], sAh + aoff + mi * (16 * TS * 4) + ks * 32);
                ldsm4(al[mi], sAl + aoff + mi * (16 * TS * 4) + ks * 32);
            }
#pragma unroll
            for (int n2 = 0; n2 < 2; ++n2) {
                ldsm4(bh2[n2], sBh + boff + n2 * (16 * TS * 4) + ks * 32);
                ldsm4(bl2[n2], sBl + boff + n2 * (16 * TS * 4) + ks * 32);
            }
#pragma unroll
            for (int ni = 0; ni < 4; ++ni) {
                const unsigned b0h = bh2[ni >> 1][(ni & 1) * 2];
                const unsigned b1h = bh2[ni >> 1][(ni & 1) * 2 + 1];
                const unsigned b0l = bl2[ni >> 1][(ni & 1) * 2];
                const unsigned b1l = bl2[ni >> 1][(ni & 1) * 2 + 1];
#pragma unroll
                for (int mi = 0; mi < 4; ++mi) {
                    mma16(c[mi][ni], ah[mi][0], ah[mi][1], ah[mi][2], ah[mi][3], b0h, b1h);
                    mma16(c[mi][ni], ah[mi][0], ah[mi][1], ah[mi][2], ah[mi][3], b0l, b1l);
                    mma16(c[mi][ni], al[mi][0], al[mi][1], al[mi][2], al[mi][3], b0h, b1h);
                }
            }
        }
        __syncthreads();
    }

#pragma unroll
    for (int mi = 0; mi < 4; ++mi)
#pragma unroll
        for (int ni = 0; ni < 4; ++ni)
#pragma unroll
            for (int hh = 0; hh < 2; ++hh) {
                const int rowg = bm0 + wm + mi * 16 + gid + hh * 8;
                const int col = bn0 + wn + ni * 8 + tig * 2;
                const float x = (c[mi][ni][hh * 2 + 0] + bias[col]) * scale;
                const float y = (c[mi][ni][hh * 2 + 1] + bias[col + 1]) * scale;
                if (mode == 0) {
                    *reinterpret_cast<float2*>(&pp.outF[z][(size_t)rowg * Dn + col]) =
                        make_float2(x, y);
                } else {
                    const int b = rowg >> 11, s = rowg & (Sn - 1);
                    const int h = col >> 6, d = col & 63;
                    if (mode == 1) {
                        const size_t idx = (((size_t)(b * Hn + h)) * Sn + s) * 32 + (d >> 1);
                        unsigned hw, lw;
                        split2(x, y, hw, lw);
                        pp.oPh[z][idx] = hw;
                        pp.oPl[z][idx] = lw;
                    } else {  // mode 2: V transposed (bh, d, s)
                        const size_t idx = (((size_t)(b * Hn + h)) * DEPn + d) * Sn + s;
                        pp.outF[z][idx] = x;
                        pp.outF[z][idx + Sn] = y;
                    }
                }
            }
}

// ---------------------------------------------------------------------------
// Fused attention, 4x2 warp tiling: warp = 32 q-rows x 64 score-cols.
// Two-pass flash; cross-warp stat combine between passes; cross-warp O
// reduction at the end. ldmatrix fragments; PV fed from softmax registers.
// ---------------------------------------------------------------------------
constexpr int QS = 36, VS = 68;
constexpr int OFF_QH = 0, OFF_QL = 4608, OFF_KH = 9216, OFF_KL = 13824;
constexpr int OFF_VTH = 18432, OFF_VTL = 22784, OFF_MSK = 27136, OFF_STAT = 27264;
constexpr int FSMB = (27264 + 512) * 4;   // 111,104 B

__global__ __launch_bounds__(256, 1) void fmha(const float* __restrict__ mask,
                                               float* __restrict__ attn) {
    extern __shared__ unsigned sm[];
    unsigned* Qh = sm + OFF_QH;
    unsigned* Ql = sm + OFF_QL;
    unsigned* Kh = sm + OFF_KH;
    unsigned* Kl = sm + OFF_KL;
    unsigned* Vth = sm + OFF_VTH;
    unsigned* Vtl = sm + OFF_VTL;
    float* Msk = reinterpret_cast<float*>(sm + OFF_MSK);
    float* Stat = reinterpret_cast<float*>(sm + OFF_STAT);

    const int bx = blockIdx.x;
    const int mt = 15 - (bx >> 5);
    const int bh = bx & 31;
    const int b = bh >> 4, h = bh & 15;
    const int tid = threadIdx.x, warp = tid >> 5, lane = tid & 31;
    const int gid = lane >> 2, tig = lane & 3;
    const int mg = warp >> 1, ng = warp & 1;   // 4 m-groups x 2 n-groups
    const int row = tid >> 1, wq = (tid & 1) * 16;

    const unsigned sQh = (unsigned)__cvta_generic_to_shared(Qh);
    const unsigned sQl = (unsigned)__cvta_generic_to_shared(Ql);
    const unsigned sKh = (unsigned)__cvta_generic_to_shared(Kh);
    const unsigned sKl = (unsigned)__cvta_generic_to_shared(Kl);
    const unsigned sVh = (unsigned)__cvta_generic_to_shared(Vth);
    const unsigned sVl = (unsigned)__cvta_generic_to_shared(Vtl);
    const unsigned aoff = ((mg * 32 + (lane & 15)) * QS + ((lane >> 4) << 2)) * 4;
    const unsigned koff =
        ((ng * 64 + (lane & 7) + ((lane & 16) ? 8 : 0)) * QS + (((lane >> 3) & 1) << 2)) * 4;
    const unsigned voff =
        (((lane & 7) + ((lane & 16) ? 8 : 0)) * VS + (((lane >> 3) & 1) << 2)) * 4;

    // load Q tile (packed hi/lo)
    {
        const size_t qb = ((size_t)bh * Sn + mt * 128 + row) * 32 + wq;
        const uint4* qh4 = reinterpret_cast<const uint4*>(g_Qph + qb);
        const uint4* ql4 = reinterpret_cast<const uint4*>(g_Qpl + qb);
#pragma unroll
        for (int u = 0; u < 4; ++u) {
            *reinterpret_cast<uint4*>(&Qh[row * QS + wq + u * 4]) = qh4[u];
            *reinterpret_cast<uint4*>(&Ql[row * QS + wq + u * 4]) = ql4[u];
        }
    }

    float rm[2][2], rl[2][2];
#pragma unroll
    for (int mi = 0; mi < 2; ++mi) {
        rm[mi][0] = rm[mi][1] = -3.0e38f;
        rl[mi][0] = rl[mi][1] = 0.f;
    }

    // ------------------------------- pass 1 -------------------------------
    for (int j = 0; j <= mt; ++j) {
        __syncthreads();
        {
            const size_t kb = ((size_t)bh * Sn + j * 128 + row) * 32 + wq;
            const uint4* kh4 = reinterpret_cast<const uint4*>(g_Kph + kb);
            const uint4* kl4 = reinterpret_cast<const uint4*>(g_Kpl + kb);
#pragma unroll
            for (int u = 0; u < 4; ++u) {
                *reinterpret_cast<uint4*>(&Kh[row * QS + wq + u * 4]) = kh4[u];
                *reinterpret_cast<uint4*>(&Kl[row * QS + wq + u * 4]) = kl4[u];
            }
            if (tid < 128) Msk[tid] = mask[(size_t)b * Sn + j * 128 + tid];
        }
        __syncthreads();

        float c[2][8][4];
#pragma unroll
        for (int mi = 0; mi < 2; ++mi)
#pragma unroll
            for (int nf = 0; nf < 8; ++nf)
#pragma unroll
                for (int e = 0; e < 4; ++e) c[mi][nf][e] = 0.f;
#pragma unroll
        for (int ks = 0; ks < 4; ++ks) {
            unsigned ah[2][4], al[2][4];
#pragma unroll
            for (int mi = 0; mi < 2; ++mi) {
                ldsm4(ah[mi], sQh + aoff + mi * (16 * QS * 4) + ks * 32);
                ldsm4(al[mi], sQl + aoff + mi * (16 * QS * 4) + ks * 32);
            }
#pragma unroll
            for (int n2 = 0; n2 < 4; ++n2) {
                unsigned kh[4], kl[4];
                ldsm4(kh, sKh + koff + n2 * (16 * QS * 4) + ks * 32);
                ldsm4(kl, sKl + koff + n2 * (16 * QS * 4) + ks * 32);
#pragma unroll
                for (int mi = 0; mi < 2; ++mi) {
                    mma16(c[mi][2 * n2], ah[mi][0], ah[mi][1], ah[mi][2], ah[mi][3], kh[0], kh[1]);
                    mma16(c[mi][2 * n2], ah[mi][0], ah[mi][1], ah[mi][2], ah[mi][3], kl[0], kl[1]);
                    mma16(c[mi][2 * n2], al[mi][0], al[mi][1], al[mi][2], al[mi][3], kh[0], kh[1]);
                    mma16(c[mi][2 * n2 + 1], ah[mi][0], ah[mi][1], ah[mi][2], ah[mi][3], kh[2], kh[3]);
                    mma16(c[mi][2 * n2 + 1], ah[mi][0], ah[mi][1], ah[mi][2], ah[mi][3], kl[2], kl[3]);
                    mma16(c[mi][2 * n2 + 1], al[mi][0], al[mi][1], al[mi][2], al[mi][3], kh[2], kh[3]);
                }
            }
        }

        float tm[2][2];
        tm[0][0] = tm[0][1] = tm[1][0] = tm[1][1] = -3.0e38f;
#pragma unroll
        for (int mi = 0; mi < 2; ++mi)
#pragma unroll
            for (int nf = 0; nf < 8; ++nf)
#pragma unroll
                for (int e = 0; e < 4; ++e) {
                    const int half = e >> 1;
                    const int cl = ng * 64 + nf * 8 + tig * 2 + (e & 1);
                    const int gcol = j * 128 + cl;
                    const int grow = mt * 128 + mg * 32 + mi * 16 + gid + half * 8;
                    const float pen = fmaxf(Msk[cl], (gcol > grow) ? 1.0f : 0.0f) * -1e17f;
                    const float s = c[mi][nf][e] + pen;
                    c[mi][nf][e] = s;
                    tm[mi][half] = fmaxf(tm[mi][half], s);
                }
#pragma unroll
        for (int mi = 0; mi < 2; ++mi)
#pragma unroll
            for (int half = 0; half < 2; ++half) {
                const float nm = fmaxf(rm[mi][half], tm[mi][half]);
                float acc = 0.f;
#pragma unroll
                for (int nf = 0; nf < 8; ++nf)
                    acc += __expf(c[mi][nf][half * 2] - nm) +
                           __expf(c[mi][nf][half * 2 + 1] - nm);
                rl[mi][half] = rl[mi][half] * __expf(rm[mi][half] - nm) + acc;
                rm[mi][half] = nm;
            }
    }

    // cross-lane (tig) stat reduction
#pragma unroll
    for (int off = 1; off < 4; off <<= 1)
#pragma unroll
        for (int mi = 0; mi < 2; ++mi)
#pragma unroll
            for (int half = 0; half < 2; ++half) {
                const float om = __shfl_xor_sync(0xffffffffu, rm[mi][half], off);
                const float ol = __shfl_xor_sync(0xffffffffu, rl[mi][half], off);
                const float nm = fmaxf(rm[mi][half], om);
                rl[mi][half] = rl[mi][half] * __expf(rm[mi][half] - nm) +
                               ol * __expf(om - nm);
                rm[mi][half] = nm;
            }

    // cross-warp (ng) stat combine via smem
    __syncthreads();
    if (tig == 0) {
#pragma unroll
        for (int mi = 0; mi < 2; ++mi)
#pragma unroll
            for (int half = 0; half < 2; ++half) {
                const int r = mg * 32 + mi * 16 + gid + half * 8;
                Stat[r * 4 + ng * 2 + 0] = rm[mi][half];
                Stat[r * 4 + ng * 2 + 1] = rl[mi][half];
            }
    }
    __syncthreads();
    float inv[2][2];
#pragma unroll
    for (int mi = 0; mi < 2; ++mi)
#pragma unroll
        for (int half = 0; half < 2; ++half) {
            const int r = mg * 32 + mi * 16 + gid + half * 8;
            const float m0 = Stat[r * 4 + 0], l0 = Stat[r * 4 + 1];
            const float m1 = Stat[r * 4 + 2], l1 = Stat[r * 4 + 3];
            const float nm = fmaxf(m0, m1);
            const float l = l0 * __expf(m0 - nm) + l1 * __expf(m1 - nm);
            rm[mi][half] = nm;
            inv[mi][half] = 1.f / l;
        }

    float o[2][8][4];
#pragma unroll
    for (int mi = 0; mi < 2; ++mi)
#pragma unroll
        for (int nf = 0; nf < 8; ++nf)
#pragma unroll
            for (int e = 0; e < 4; ++e) o[mi][nf][e] = 0.f;

    // ------------------------------- pass 2 -------------------------------
    for (int j = 0; j <= mt; ++j) {
        __syncthreads();
        {
            const size_t kb = ((size_t)bh * Sn + j * 128 + row) * 32 + wq;
            const uint4* kh4 = reinterpret_cast<const uint4*>(g_Kph + kb);
            const uint4* kl4 = reinterpret_cast<const uint4*>(g_Kpl + kb);
#pragma unroll
            for (int u = 0; u < 4; ++u) {
                *reinterpret_cast<uint4*>(&Kh[row * QS + wq + u * 4]) = kh4[u];
                *reinterpret_cast<uint4*>(&Kl[row * QS + wq + u * 4]) = kl4[u];
            }
            // V^T tile: 64 d-rows x 128 s; float4 loads cover all 4096 words
#pragma unroll
            for (int u = 0; u < 8; ++u) {
                const int flat = tid + u * 256;      // 0..2047
                const int d = flat >> 5;             // 0..63
                const int g = flat & 31;             // float4 group within row
                const float4 vv = *reinterpret_cast<const float4*>(
                    g_Vt + ((size_t)bh * DEPn + d) * Sn + j * 128 + 4 * g);
                unsigned h0, l0, h1, l1;
                split2(vv.x, vv.y, h0, l0);
                split2(vv.z, vv.w, h1, l1);
                Vth[d * VS + 2 * g]     = h0;
                Vth[d * VS + 2 * g + 1] = h1;
                Vtl[d * VS + 2 * g]     = l0;
                Vtl[d * VS + 2 * g + 1] = l1;
            }
            if (tid < 128) Msk[tid] = mask[(size_t)b * Sn + j * 128 + tid];
        }
        __syncthreads();

        float c[2][8][4];
#pragma unroll
        for (int mi = 0; mi < 2; ++mi)
#pragma unroll
            for (int nf = 0; nf < 8; ++nf)
#pragma unroll
                for (int e = 0; e < 4; ++e) c[mi][nf][e] = 0.f;
#pragma unroll
        for (int ks = 0; ks < 4; ++ks) {
            unsigned ah[2][4], al[2][4];
#pragma unroll
            for (int mi = 0; mi < 2; ++mi) {
                ldsm4(ah[mi], sQh + aoff + mi * (16 * QS * 4) + ks * 32);
                ldsm4(al[mi], sQl + aoff + mi * (16 * QS * 4) + ks * 32);
            }
#pragma unroll
            for (int n2 = 0; n2 < 4; ++n2) {
                unsigned kh[4], kl[4];
                ldsm4(kh, sKh + koff + n2 * (16 * QS * 4) + ks * 32);
                ldsm4(kl, sKl + koff + n2 * (16 * QS * 4) + ks * 32);
#pragma unroll
                for (int mi = 0; mi < 2; ++mi) {
                    mma16(c[mi][2 * n2], ah[mi][0], ah[mi][1], ah[mi][2], ah[mi][3], kh[0], kh[1]);
                    mma16(c[mi][2 * n2], ah[mi][0], ah[mi][1], ah[mi][2], ah[mi][3], kl[0], kl[1]);
                    mma16(c[mi][2 * n2], al[mi][0], al[mi][1], al[mi][2], al[mi][3], kh[0], kh[1]);
                    mma16(c[mi][2 * n2 + 1], ah[mi][0], ah[mi][1], ah[mi][2], ah[mi][3], kh[2], kh[3]);
                    mma16(c[mi][2 * n2 + 1], ah[mi][0], ah[mi][1], ah[mi][2], ah[mi][3], kl[2], kl[3]);
                    mma16(c[mi][2 * n2 + 1], al[mi][0], al[mi][1], al[mi][2], al[mi][3], kh[2], kh[3]);
                }
            }
        }

        // softmax (exact, consistent with pass 1)
#pragma unroll
        for (int mi = 0; mi < 2; ++mi)
#pragma unroll
            for (int nf = 0; nf < 8; ++nf)
#pragma unroll
                for (int e = 0; e < 4; ++e) {
                    const int half = e >> 1;
                    const int cl = ng * 64 + nf * 8 + tig * 2 + (e & 1);
                    const int gcol = j * 128 + cl;
                    const int grow = mt * 128 + mg * 32 + mi * 16 + gid + half * 8;
                    const float pen = fmaxf(Msk[cl], (gcol > grow) ? 1.0f : 0.0f) * -1e17f;
                    c[mi][nf][e] =
                        __expf(c[mi][nf][e] + pen - rm[mi][half]) * inv[mi][half];
                }

        // attn write straight from registers
        float* attnp = attn + ((size_t)bh * Sn + mt * 128) * Sn + (size_t)j * 128;
#pragma unroll
        for (int mi = 0; mi < 2; ++mi)
#pragma unroll
            for (int nf = 0; nf < 8; ++nf)
#pragma unroll
                for (int half = 0; half < 2; ++half) {
                    const int r = mg * 32 + mi * 16 + gid + half * 8;
                    *reinterpret_cast<float2*>(
                        attnp + (size_t)r * Sn + ng * 64 + nf * 8 + tig * 2) =
                        make_float2(c[mi][nf][half * 2], c[mi][nf][half * 2 + 1]);
                }

        // O += P @ V over this warp's 64 k-cols (3-term bf16)
#pragma unroll
        for (int cHl = 0; cHl < 4; ++cHl) {
            const int kchunk = ng * 4 + cHl;
            unsigned pah[2][4], pal[2][4];
#pragma unroll
            for (int mi = 0; mi < 2; ++mi) {
                split2(c[mi][2 * cHl][0], c[mi][2 * cHl][1], pah[mi][0], pal[mi][0]);
                split2(c[mi][2 * cHl][2], c[mi][2 * cHl][3], pah[mi][1], pal[mi][1]);
                split2(c[mi][2 * cHl + 1][0], c[mi][2 * cHl + 1][1], pah[mi][2], pal[mi][2]);
                split2(c[mi][2 * cHl + 1][2], c[mi][2 * cHl + 1][3], pah[mi][3], pal[mi][3]);
            }
#pragma unroll
            for (int n2 = 0; n2 < 4; ++n2) {
                unsigned vh[4], vl[4];
                ldsm4(vh, sVh + voff + n2 * (16 * VS * 4) + kchunk * 32);
                ldsm4(vl, sVl + voff + n2 * (16 * VS * 4) + kchunk * 32);
#pragma unroll
                for (int mi = 0; mi < 2; ++mi) {
                    mma16(o[mi][2 * n2], pah[mi][0], pah[mi][1], pah[mi][2], pah[mi][3], vh[0], vh[1]);
                    mma16(o[mi][2 * n2], pah[mi][0], pah[mi][1], pah[mi][2], pah[mi][3], vl[0], vl[1]);
                    mma16(o[mi][2 * n2], pal[mi][0], pal[mi][1], pal[mi][2], pal[mi][3], vh[0], vh[1]);
                    mma16(o[mi][2 * n2 + 1], pah[mi][0], pah[mi][1], pah[mi][2], pah[mi][3], vh[2], vh[3]);
                    mma16(o[mi][2 * n2 + 1], pah[mi][0], pah[mi][1], pah[mi][2], pah[mi][3], vl[2], vl[3]);
                    mma16(o[mi][2 * n2 + 1], pal[mi][0], pal[mi][1], pal[mi][2], pal[mi][3], vh[2], vh[3]);
                }
            }
        }
    }

    // zero-fill fully-masked tiles
    for (int j = mt + 1; j < 16; ++j) {
        float* attnp = attn + ((size_t)bh * Sn + mt * 128) * Sn + (size_t)j * 128;
        const float4 z4 = make_float4(0.f, 0.f, 0.f, 0.f);
#pragma unroll
        for (int u = 0; u < 16; ++u) {
            const int r = warp * 16 + u;
            *reinterpret_cast<float4*>(attnp + (size_t)r * Sn + lane * 4) = z4;
        }
    }

    // cross-warp O reduction (ng pair) through smem (reuse Q/K region)
    __syncthreads();
    float* Ored = reinterpret_cast<float*>(sm);
    if (ng == 1) {
#pragma unroll
        for (int mi = 0; mi < 2; ++mi)
#pragma unroll
            for (int nf = 0; nf < 8; ++nf)
#pragma unroll
                for (int e = 0; e < 4; ++e)
                    Ored[(mg * 32 + lane) * 65 + mi * 32 + nf * 4 + e] = o[mi][nf][e];
    }
    __syncthreads();
    if (ng == 0) {
#pragma unroll
        for (int mi = 0; mi < 2; ++mi)
#pragma unroll
            for (int nf = 0; nf < 8; ++nf)
#pragma unroll
                for (int e = 0; e < 4; ++e)
                    o[mi][nf][e] += Ored[(mg * 32 + lane) * 65 + mi * 32 + nf * 4 + e];

        // O epilogue: packed bf16 hi/lo for the final projection
#pragma unroll
        for (int mi = 0; mi < 2; ++mi)
#pragma unroll
            for (int nf = 0; nf < 8; ++nf)
#pragma unroll
                for (int half = 0; half < 2; ++half) {
                    const int s = mt * 128 + mg * 32 + mi * 16 + gid + half * 8;
                    const size_t idx =
                        ((size_t)(b * Sn + s)) * 512 + h * 32 + nf * 4 + tig;
                    unsigned hw, lw;
                    split2(o[mi][nf][half * 2], o[mi][nf][half * 2 + 1], hw, lw);
                    g_Oph[idx] = hw;
                    g_Opl[idx] = lw;
                }
    }
}

// ---------------------------------------------------------------------------
extern "C" void kernel_launch(void* const* d_in, const int* in_sizes, int n_in,
                              void* d_out, int out_size) {
    const float* v    = (const float*)d_in[0];
    const float* k    = (const float*)d_in[1];
    const float* q    = (const float*)d_in[2];
    const float* mask = (const float*)d_in[3];
    const float* Wq = (const float*)d_in[4],  *bq = (const float*)d_in[5];
    const float* Wk = (const float*)d_in[6],  *bk = (const float*)d_in[7];
    const float* Wv = (const float*)d_in[8],  *bv = (const float*)d_in[9];
    const float* Wo = (const float*)d_in[10], *bo = (const float*)d_in[11];

    float* out  = (float*)d_out;
    float* attn = out + OUT_ELEMS;

    void *aph, *apl, *wth, *wtl, *qph, *qpl, *kph, *kpl, *vt, *oph, *opl;
    cudaGetSymbolAddress(&aph, g_Aph);
    cudaGetSymbolAddress(&apl, g_Apl);
    cudaGetSymbolAddress(&wth, g_Wth);
    cudaGetSymbolAddress(&wtl, g_Wtl);
    cudaGetSymbolAddress(&qph, g_Qph);
    cudaGetSymbolAddress(&qpl, g_Qpl);
    cudaGetSymbolAddress(&kph, g_Kph);
    cudaGetSymbolAddress(&kpl, g_Kpl);
    cudaGetSymbolAddress(&vt, g_Vt);
    cudaGetSymbolAddress(&oph, g_Oph);
    cudaGetSymbolAddress(&opl, g_Opl);

    cudaFuncSetAttribute(proj_gemm, cudaFuncAttributeMaxDynamicSharedMemorySize, PSMB);
    cudaFuncSetAttribute(fmha, cudaFuncAttributeMaxDynamicSharedMemorySize, FSMB);

    split_act<<<dim3((unsigned)(AW / 4 / 256), 3), 256>>>(q, k, v);
    W4 ws;
    ws.w[0] = Wq; ws.w[1] = Wk; ws.w[2] = Wv; ws.w[3] = Wo;
    transpose_split<<<dim3(32, 32, 4), 256>>>(ws);

    PP3 p1;
    for (int z = 0; z < 3; ++z) {
        p1.Ah[z] = (const unsigned*)aph + (size_t)z * AW;
        p1.Al[z] = (const unsigned*)apl + (size_t)z * AW;
        p1.Bh[z] = (const unsigned*)wth + (size_t)z * WW;
        p1.Bl[z] = (const unsigned*)wtl + (size_t)z * WW;
        p1.outF[z] = nullptr;
        p1.oPh[z] = nullptr;
        p1.oPl[z] = nullptr;
    }
    p1.bias[0] = bq; p1.scale[0] = 0.125f; p1.mode[0] = 1;
    p1.oPh[0] = (unsigned*)qph; p1.oPl[0] = (unsigned*)qpl;
    p1.bias[1] = bk; p1.scale[1] = 1.0f;   p1.mode[1] = 1;
    p1.oPh[1] = (unsigned*)kph; p1.oPl[1] = (unsigned*)kpl;
    p1.bias[2] = bv; p1.scale[2] = 1.0f;   p1.mode[2] = 2;
    p1.outF[2] = (float*)vt;
    proj_gemm<<<dim3(8, 32, 3), 256, PSMB>>>(p1);

    fmha<<<512, 256, FSMB>>>(mask, attn);

    PP3 p2;
    for (int z = 0; z < 3; ++z) {
        p2.Ah[z] = (const unsigned*)oph;
        p2.Al[z] = (const unsigned*)opl;
        p2.Bh[z] = (const unsigned*)wth + (size_t)3 * WW;
        p2.Bl[z] = (const unsigned*)wtl + (size_t)3 * WW;
        p2.bias[z] = bo;
        p2.scale[z] = 1.0f;
        p2.mode[z] = 0;
        p2.outF[z] = out;
        p2.oPh[z] = nullptr;
        p2.oPl[z] = nullptr;
    }
    proj_gemm<<<dim3(8, 32, 1), 256, PSMB>>>(p2);
}